// round 1
// baseline (speedup 1.0000x reference)
#include <cuda_runtime.h>
#include <math.h>

// Problem constants
#define QS 256
#define LS 2048
#define NB 64
#define SS 26
#define NPOST (NB * LS * QS)   // 33,554,432 post elements
#define ROWPITCH 132           // padded shared row pitch (floats) to avoid bank conflicts
#define EM_ROWS 64

// ---------------------------------------------------------------------------
// Scratch (static __device__ arrays; no allocation allowed in kernel_launch)
// ---------------------------------------------------------------------------
__device__ float g_expA[QS * QS];     // exp(log_A), row-major [j][i]
__device__ float g_expAT[QS * QS];    // transpose: g_expAT[j*QS+i] = expA[i][j]
__device__ float g_expB[QS * 32];     // exp(log_B), padded [q][32]
__device__ float g_pi[QS];            // exp(log_pi)
__device__ float g_emit[NPOST];       // emissions, [b][l][q]
__device__ float g_alpha[NPOST];      // normalized forward probs
__device__ float g_beta[NPOST];       // normalized backward probs
__device__ float g_Ca[NB * LS];       // forward  log-scales (cumulative)
__device__ float g_Cb[NB * LS];       // backward log-scales (cumulative)

// ---------------------------------------------------------------------------
// Kernel 0: precompute exp() of parameters
// ---------------------------------------------------------------------------
__global__ void precompute_kernel(const float* __restrict__ log_A,
                                  const float* __restrict__ log_pi,
                                  const float* __restrict__ log_B) {
    int idx = blockIdx.x * 256 + threadIdx.x;
    if (blockIdx.x < 256) {
        float v = expf(log_A[idx]);
        g_expA[idx] = v;
        int j = idx >> 8, i = idx & 255;
        g_expAT[i * QS + j] = v;
    } else if (blockIdx.x < 282) {
        int k = idx - 65536;               // 0 .. 6655
        if (k < QS * SS) {
            int q = k / SS, s = k - q * SS;
            g_expB[q * 32 + s] = expf(log_B[k]);
        }
    } else {
        if (threadIdx.x < QS) g_pi[threadIdx.x] = expf(log_pi[threadIdx.x]);
    }
}

// ---------------------------------------------------------------------------
// Kernel 1: emission GEMM  emit[b,l,q] = sum_s inputs[b,l,s] * expB[q,s]
// ---------------------------------------------------------------------------
__global__ void __launch_bounds__(256) emission_kernel(const float* __restrict__ inputs) {
    __shared__ float in_sh[EM_ROWS][SS];
    int tid = threadIdx.x;
    int row0 = blockIdx.x * EM_ROWS;       // row = b*LS + l

    for (int i = tid; i < EM_ROWS * SS; i += 256) {
        in_sh[i / SS][i % SS] = inputs[row0 * SS + i];
    }
    float eb[SS];
#pragma unroll
    for (int s = 0; s < SS; s++) eb[s] = g_expB[tid * 32 + s];
    __syncthreads();

#pragma unroll 4
    for (int r = 0; r < EM_ROWS; r++) {
        float acc = 0.0f;
#pragma unroll
        for (int s = 0; s < SS; s++) acc = fmaf(in_sh[r][s], eb[s], acc);
        g_emit[(size_t)(row0 + r) * QS + tid] = acc;
    }
}

// ---------------------------------------------------------------------------
// Recursion helpers
// ---------------------------------------------------------------------------
__device__ __forceinline__ float block_sum(float v, float* red, int tid) {
#pragma unroll
    for (int o = 16; o > 0; o >>= 1) v += __shfl_xor_sync(0xffffffffu, v, o);
    if ((tid & 31) == 0) red[tid >> 5] = v;
    __syncthreads();
    float s = 0.0f;
#pragma unroll
    for (int w = 0; w < 8; w++) s += red[w];
    return s;
}

// v[i] = sum_{j<128} p[j]*Ash_row[j]  +  sum_{k<128} p[128+k]*Areg[k]
__device__ __forceinline__ float matvec256(const float* __restrict__ Ash_row,
                                           const float* __restrict__ Areg,
                                           const float4* __restrict__ p4) {
    float a0 = 0.f, a1 = 0.f, a2 = 0.f, a3 = 0.f;
    const float4* Ar4 = reinterpret_cast<const float4*>(Ash_row);
#pragma unroll
    for (int j = 0; j < 32; j++) {
        float4 a = Ar4[j];
        float4 p = p4[j];
        a0 = fmaf(a.x, p.x, a0);
        a1 = fmaf(a.y, p.y, a1);
        a2 = fmaf(a.z, p.z, a2);
        a3 = fmaf(a.w, p.w, a3);
    }
#pragma unroll
    for (int k = 0; k < 32; k++) {
        float4 p = p4[32 + k];
        a0 = fmaf(Areg[4 * k + 0], p.x, a0);
        a1 = fmaf(Areg[4 * k + 1], p.y, a1);
        a2 = fmaf(Areg[4 * k + 2], p.z, a2);
        a3 = fmaf(Areg[4 * k + 3], p.w, a3);
    }
    return (a0 + a1) + (a2 + a3);
}

// ---------------------------------------------------------------------------
// Kernel 2: forward/backward recursions (scaled, linear domain).
// Block 0..63  : forward  chain for batch b = blockIdx
// Block 64..127: backward chain for batch b = blockIdx-64 (uses expA^T)
// ---------------------------------------------------------------------------
extern __shared__ float sh[];

__global__ void __launch_bounds__(256, 1) fb_kernel() {
    float* Ash  = sh;                     // 256 rows * ROWPITCH floats (per-thread rows)
    float* p_sh = sh + QS * ROWPITCH;     // 256 floats (current probability vector / w)
    float* red  = p_sh + QS;              // 8 floats reduction scratch

    int tid = threadIdx.x;
    int bx = blockIdx.x;
    bool fwd = (bx < NB);
    int b = fwd ? bx : bx - NB;
    const float* Ag = fwd ? g_expA : g_expAT;

    // Rows 0..127 of A (this thread's column segment) -> private shared row
    float* myrow = Ash + tid * ROWPITCH;
    for (int j = 0; j < 128; j++)
        myrow[j] = Ag[j * QS + tid];

    // Rows 128..255 -> registers
    float Areg[128];
#pragma unroll
    for (int k = 0; k < 128; k++) Areg[k] = Ag[(128 + k) * QS + tid];

    const float* em_b = g_emit + (size_t)b * LS * QS;
    float* st_b = (fwd ? g_alpha : g_beta) + (size_t)b * LS * QS;
    float* C_b  = (fwd ? g_Ca : g_Cb) + b * LS;

    const float4* p4 = reinterpret_cast<const float4*>(p_sh);
    double C;

    if (fwd) {
        // t = 0 : alpha0 = pi * e0, normalized
        float v = g_pi[tid] * em_b[tid];
        float s = block_sum(v, red, tid);
        float p = v * (1.0f / s);
        C = (double)logf(s);
        p_sh[tid] = p;
        st_b[tid] = p;
        if (tid == 0) C_b[0] = (float)C;
        __syncthreads();

        for (int t = 1; t < LS; t++) {
            float e  = em_b[(size_t)t * QS + tid];            // prefetch (hidden by matvec)
            float mv = matvec256(myrow, Areg, p4);
            float v2 = mv * e;
            float s2 = block_sum(v2, red, tid);               // contains __syncthreads
            float p2 = v2 * (1.0f / s2);
            C += (double)logf(s2);
            p_sh[tid] = p2;                                    // safe: all reads done
            st_b[(size_t)t * QS + tid] = p2;
            if (tid == 0) C_b[t] = (float)C;
            __syncthreads();
        }
    } else {
        // t = L-1 : beta = 1  ->  normalized q = 1/Q, C = log(Q)
        const float q0 = 1.0f / 256.0f;
        C = 5.545177444479562;                                 // log(256)
        st_b[(size_t)(LS - 1) * QS + tid] = q0;
        if (tid == 0) C_b[LS - 1] = (float)C;
        p_sh[tid] = em_b[(size_t)(LS - 1) * QS + tid] * q0;    // w = e_{t+1} * q_{t+1}
        __syncthreads();

        for (int t = LS - 2; t >= 0; t--) {
            float e  = em_b[(size_t)t * QS + tid];             // emit_t for NEXT step's w
            float mv = matvec256(myrow, Areg, p4);             // sum_j A[i][j] w[j]
            float s2 = block_sum(mv, red, tid);
            float q2 = mv * (1.0f / s2);
            C += (double)logf(s2);
            st_b[(size_t)t * QS + tid] = q2;
            if (tid == 0) C_b[t] = (float)C;
            p_sh[tid] = e * q2;                                // w for step t-1
            __syncthreads();
        }
    }
}

// ---------------------------------------------------------------------------
// Kernel 3: posterior + loglik output
// post[b,t,i] = log(alpha~) + log(beta~) + Ca[b,t] + Cb[b,t] - loglik[b]
// loglik[b]   = Ca[b, L-1]
// ---------------------------------------------------------------------------
__global__ void posterior_kernel(float* __restrict__ out, int out_size) {
    int idx = blockIdx.x * 256 + threadIdx.x;  // 0 .. NPOST-1 exactly
    int bt = idx >> 8;                          // b*LS + t
    int b  = bt >> 11;                          // / LS
    float a  = g_alpha[idx];
    float be = g_beta[idx];
    float c  = g_Ca[bt] + g_Cb[bt] - g_Ca[(b << 11) + (LS - 1)];
    out[idx] = logf(a) + logf(be) + c;
    if (idx < NB && out_size >= NPOST + NB)
        out[NPOST + idx] = g_Ca[idx * LS + (LS - 1)];
}

// ---------------------------------------------------------------------------
// Launch
// ---------------------------------------------------------------------------
extern "C" void kernel_launch(void* const* d_in, const int* in_sizes, int n_in,
                              void* d_out, int out_size) {
    const float* inputs = (const float*)d_in[0];   // (1,64,2048,26)
    const float* log_A  = (const float*)d_in[1];   // (1,256,256)
    const float* log_pi = (const float*)d_in[2];   // (1,256)
    const float* log_B  = (const float*)d_in[3];   // (1,256,26)
    float* out = (float*)d_out;

    precompute_kernel<<<283, 256>>>(log_A, log_pi, log_B);
    emission_kernel<<<(NB * LS) / EM_ROWS, 256>>>(inputs);

    int smem = (QS * ROWPITCH + QS + 16) * (int)sizeof(float);
    cudaFuncSetAttribute(fb_kernel, cudaFuncAttributeMaxDynamicSharedMemorySize, smem);
    fb_kernel<<<2 * NB, 256, smem>>>();

    posterior_kernel<<<NPOST / 256, 256>>>(out, out_size);
}

// round 2
// speedup vs baseline: 2.0564x; 2.0564x over previous
#include <cuda_runtime.h>
#include <cuda_bf16.h>
#include <math.h>

// Problem constants
#define QS 256
#define LS 2048
#define NB 64
#define SS 26
#define NPOST (NB * LS * QS)     // 33,554,432
#define EM_ROWS 64

// A split: rows 0..159 in registers (fp32), rows 160..255 in shared (bf16)
#define REGROWS 160
#define SHROWS  96
#define ROWPITCH_U32 52          // 48 payload words + 4 pad (208B) -> conflict-free LDS.128
#define RENORM_MASK 15

// ---------------------------------------------------------------------------
// Device scratch
// ---------------------------------------------------------------------------
__device__ float g_expA[QS * QS];     // exp(log_A)  [j][i]
__device__ float g_expAT[QS * QS];    // transpose
__device__ float g_expB[QS * 32];     // exp(log_B) padded
__device__ float g_pi[QS];
__device__ float g_emit[NPOST];       // [b][l][q]
__device__ float g_alpha[NPOST];      // unnormalized-within-block alpha~
__device__ float g_beta[NPOST];       // unnormalized-within-block beta~
__device__ float g_Ca[NB * LS];       // piecewise-constant forward log-scale
__device__ float g_Cb[NB * LS];       // piecewise-constant backward log-scale
__device__ float g_loglik[NB];

// ---------------------------------------------------------------------------
// f32x2 helpers (sm_103a packed fp32 math)
// ---------------------------------------------------------------------------
__device__ __forceinline__ unsigned long long pk(float x, float y) {
    unsigned long long r;
    asm("mov.b64 %0, {%1,%2};" : "=l"(r) : "f"(x), "f"(y));
    return r;
}
__device__ __forceinline__ void ffma2(unsigned long long& c,
                                      unsigned long long a,
                                      unsigned long long b) {
    asm("fma.rn.f32x2 %0, %1, %2, %0;" : "+l"(c) : "l"(a), "l"(b));
}
__device__ __forceinline__ float2 unpk(unsigned long long u) {
    float lo, hi;
    asm("mov.b64 {%0,%1}, %2;" : "=f"(lo), "=f"(hi) : "l"(u));
    return make_float2(lo, hi);
}
// bf16x2 word -> packed f32x2 (exact widening): lo = w<<16, hi = w & 0xffff0000
__device__ __forceinline__ unsigned long long bf2f(unsigned int w) {
    unsigned int lo = w << 16;
    unsigned int hi = w & 0xffff0000u;
    unsigned long long r;
    asm("mov.b64 %0, {%1,%2};" : "=l"(r) : "r"(lo), "r"(hi));
    return r;
}

// ---------------------------------------------------------------------------
// Kernel 0: exp() of parameters
// ---------------------------------------------------------------------------
__global__ void precompute_kernel(const float* __restrict__ log_A,
                                  const float* __restrict__ log_pi,
                                  const float* __restrict__ log_B) {
    int idx = blockIdx.x * 256 + threadIdx.x;
    if (blockIdx.x < 256) {
        float v = expf(log_A[idx]);
        g_expA[idx] = v;
        int j = idx >> 8, i = idx & 255;
        g_expAT[i * QS + j] = v;
    } else if (blockIdx.x < 282) {
        int k = idx - 65536;
        if (k < QS * SS) {
            int q = k / SS, s = k - q * SS;
            g_expB[q * 32 + s] = expf(log_B[k]);
        }
    } else {
        if (threadIdx.x < QS) g_pi[threadIdx.x] = expf(log_pi[threadIdx.x]);
    }
}

// ---------------------------------------------------------------------------
// Kernel 1: emission GEMM  emit[b,l,q] = sum_s inputs[b,l,s] * expB[q,s]
// ---------------------------------------------------------------------------
__global__ void __launch_bounds__(256) emission_kernel(const float* __restrict__ inputs) {
    __shared__ float in_sh[EM_ROWS][SS];
    int tid = threadIdx.x;
    int row0 = blockIdx.x * EM_ROWS;

    for (int i = tid; i < EM_ROWS * SS; i += 256)
        in_sh[i / SS][i % SS] = inputs[row0 * SS + i];
    float eb[SS];
#pragma unroll
    for (int s = 0; s < SS; s++) eb[s] = g_expB[tid * 32 + s];
    __syncthreads();

#pragma unroll 4
    for (int r = 0; r < EM_ROWS; r++) {
        float acc = 0.0f;
#pragma unroll
        for (int s = 0; s < SS; s++) acc = fmaf(in_sh[r][s], eb[s], acc);
        g_emit[(size_t)(row0 + r) * QS + tid] = acc;
    }
}

// ---------------------------------------------------------------------------
// Block reduction (only on renorm steps)
// ---------------------------------------------------------------------------
__device__ __forceinline__ float block_sum(float v, float* red, int tid) {
#pragma unroll
    for (int o = 16; o > 0; o >>= 1) v += __shfl_xor_sync(0xffffffffu, v, o);
    if ((tid & 31) == 0) red[tid >> 5] = v;
    __syncthreads();
    float s = 0.0f;
#pragma unroll
    for (int w = 0; w < 8; w++) s += red[w];
    return s;
}

// mv[i] = sum_{j<160} p[j]*Areg + sum_{j in 160..255} p[j]*Ash(bf16)
__device__ __forceinline__ float matvec256(const unsigned long long* __restrict__ Areg,
                                           const uint4* __restrict__ arow,
                                           const float4* __restrict__ pc4) {
    unsigned long long acc0 = 0ull, acc1 = 0ull;
#pragma unroll
    for (int k = 0; k < 40; k++) {
        float4 p = pc4[k];
        ffma2(acc0, Areg[2 * k],     pk(p.x, p.y));
        ffma2(acc1, Areg[2 * k + 1], pk(p.z, p.w));
    }
#pragma unroll
    for (int k = 0; k < 12; k++) {
        uint4 w = arow[k];
        float4 pa = pc4[40 + 2 * k];
        float4 pb = pc4[40 + 2 * k + 1];
        ffma2(acc0, bf2f(w.x), pk(pa.x, pa.y));
        ffma2(acc1, bf2f(w.y), pk(pa.z, pa.w));
        ffma2(acc0, bf2f(w.z), pk(pb.x, pb.y));
        ffma2(acc1, bf2f(w.w), pk(pb.z, pb.w));
    }
    float2 a0 = unpk(acc0), a1 = unpk(acc1);
    return (a0.x + a1.x) + (a0.y + a1.y);
}

// ---------------------------------------------------------------------------
// Kernel 2: scaled forward/backward with deferred renormalization.
// Block 0..63 forward chain b; block 64..127 backward chain b-64.
// ---------------------------------------------------------------------------
extern __shared__ float sh[];

#define SH_A_U32   ((unsigned int*)sh)
#define SH_P(buf)  (sh + QS * ROWPITCH_U32 + (buf) * QS)
#define SH_RED     (sh + QS * ROWPITCH_U32 + 2 * QS)

__global__ void __launch_bounds__(256, 1) fb_kernel() {
    int tid = threadIdx.x;
    int bx = blockIdx.x;
    bool fwd = (bx < NB);
    int b = fwd ? bx : bx - NB;
    const float* Ag = fwd ? g_expA : g_expAT;

    // rows 0..159 -> fp32 register pairs (exact)
    unsigned long long Areg[REGROWS / 2];
#pragma unroll
    for (int k = 0; k < REGROWS / 2; k++)
        Areg[k] = pk(Ag[(2 * k) * QS + tid], Ag[(2 * k + 1) * QS + tid]);

    // rows 160..255 -> bf16 pairs in this thread's private shared row
    unsigned int* myrow = SH_A_U32 + tid * ROWPITCH_U32;
    for (int m = 0; m < SHROWS / 2; m++) {
        __nv_bfloat16 b0 = __float2bfloat16(Ag[(REGROWS + 2 * m) * QS + tid]);
        __nv_bfloat16 b1 = __float2bfloat16(Ag[(REGROWS + 2 * m + 1) * QS + tid]);
        myrow[m] = (unsigned int)__bfloat16_as_ushort(b0) |
                   ((unsigned int)__bfloat16_as_ushort(b1) << 16);
    }
    const uint4* arow = (const uint4*)myrow;

    const float* em_b = g_emit + (size_t)b * LS * QS;
    float* st_b = (fwd ? g_alpha : g_beta) + (size_t)b * LS * QS;
    float* C_b  = (fwd ? g_Ca : g_Cb) + b * LS;
    float* red  = SH_RED;

    double C = 0.0;
    int cur = 0;

    if (fwd) {
        // t = 0
        float v = g_pi[tid] * em_b[tid];
        st_b[tid] = v;
        if (tid == 0) C_b[0] = 0.0f;
        SH_P(0)[tid] = v;
        __syncthreads();

        for (int t = 1; t < LS; t++) {
            float e  = em_b[(size_t)t * QS + tid];
            float mv = matvec256(Areg, arow, (const float4*)SH_P(cur));
            float v2 = mv * e;
            st_b[(size_t)t * QS + tid] = v2;
            if (tid == 0) C_b[t] = (float)C;
            float pn = v2;
            if ((t & RENORM_MASK) == RENORM_MASK) {
                float s = block_sum(v2, red, tid);
                pn = v2 * (1.0f / s);
                if (t == LS - 1 && tid == 0)
                    g_loglik[b] = (float)(C + (double)logf(s));
                C += (double)logf(s);
            }
            SH_P(cur ^ 1)[tid] = pn;
            __syncthreads();
            cur ^= 1;
        }
    } else {
        // t = L-1 : beta = 1 (unnormalized), scale 0
        st_b[(size_t)(LS - 1) * QS + tid] = 1.0f;
        if (tid == 0) C_b[LS - 1] = 0.0f;
        SH_P(0)[tid] = em_b[(size_t)(LS - 1) * QS + tid];  // w = e_{t+1} * beta~_{t+1}
        __syncthreads();

        for (int t = LS - 2; t >= 0; t--) {
            float e  = em_b[(size_t)t * QS + tid];
            float v  = matvec256(Areg, arow, (const float4*)SH_P(cur));
            st_b[(size_t)t * QS + tid] = v;
            if (tid == 0) C_b[t] = (float)C;
            float q = v;
            if ((t & RENORM_MASK) == 0) {
                float s = block_sum(v, red, tid);
                q = v * (1.0f / s);
                C += (double)logf(s);
            }
            SH_P(cur ^ 1)[tid] = e * q;
            __syncthreads();
            cur ^= 1;
        }
    }
}

// ---------------------------------------------------------------------------
// Kernel 3: posterior + loglik (float4, single log per element)
// ---------------------------------------------------------------------------
__global__ void __launch_bounds__(256) posterior_kernel(float* __restrict__ out, int out_size) {
    int i4 = blockIdx.x * 256 + threadIdx.x;   // 0 .. NPOST/4-1
    int idx = i4 << 2;
    int bt = idx >> 8;
    int b  = bt >> 11;
    float4 a  = *(const float4*)(g_alpha + idx);
    float4 be = *(const float4*)(g_beta + idx);
    float c = g_Ca[bt] + g_Cb[bt] - g_loglik[b];
    float4 o;
    o.x = logf(a.x * be.x) + c;
    o.y = logf(a.y * be.y) + c;
    o.z = logf(a.z * be.z) + c;
    o.w = logf(a.w * be.w) + c;
    *(float4*)(out + idx) = o;
    if (i4 < NB && out_size >= NPOST + NB)
        out[NPOST + i4] = g_loglik[i4];
}

// ---------------------------------------------------------------------------
// Launch
// ---------------------------------------------------------------------------
extern "C" void kernel_launch(void* const* d_in, const int* in_sizes, int n_in,
                              void* d_out, int out_size) {
    const float* inputs = (const float*)d_in[0];   // (1,64,2048,26)
    const float* log_A  = (const float*)d_in[1];   // (1,256,256)
    const float* log_pi = (const float*)d_in[2];   // (1,256)
    const float* log_B  = (const float*)d_in[3];   // (1,256,26)
    float* out = (float*)d_out;

    precompute_kernel<<<283, 256>>>(log_A, log_pi, log_B);
    emission_kernel<<<(NB * LS) / EM_ROWS, 256>>>(inputs);

    int smem = (QS * ROWPITCH_U32 + 2 * QS + 16) * (int)sizeof(float);
    cudaFuncSetAttribute(fb_kernel, cudaFuncAttributeMaxDynamicSharedMemorySize, smem);
    fb_kernel<<<2 * NB, 256, smem>>>();

    posterior_kernel<<<NPOST / 1024, 256>>>(out, out_size);
}